// round 1
// baseline (speedup 1.0000x reference)
#include <cuda_runtime.h>
#include <math.h>

#define TT   8192
#define EE   1024
#define HH   16
#define DD   64
#define NSEG 8
#define LL   1024

// Scratch (device globals — no allocation allowed in kernel_launch)
__device__ float g_q [TT * EE];
__device__ float g_k [TT * EE];
__device__ float g_v [TT * EE];
__device__ float g_ao[TT * EE];

// ---------------------------------------------------------------------------
// C[M,N] = A[M,K] @ B[N,K]^T + bias.   M = 8192, N = K = 1024.
// 128x128 block tile, BK=16, 256 threads, 8x8 per thread.
// ---------------------------------------------------------------------------
__global__ __launch_bounds__(256, 2)
void gemm_nt(const float* __restrict__ A, const float* __restrict__ B,
             const float* __restrict__ bias, float* __restrict__ C)
{
    __shared__ float As[16][132];
    __shared__ float Bs[16][132];

    const int tid = threadIdx.x;
    const int ty  = tid >> 4;        // 0..15
    const int tx  = tid & 15;        // 0..15
    const int rowBase = blockIdx.y * 128;
    const int colBase = blockIdx.x * 128;

    const int lr = tid >> 2;         // 0..63 loader row
    const int lc = (tid & 3) * 4;    // 0,4,8,12 loader k-offset

    float acc[8][8];
#pragma unroll
    for (int i = 0; i < 8; i++)
#pragma unroll
        for (int j = 0; j < 8; j++) acc[i][j] = 0.f;

    const float* Aptr = A + (size_t)(rowBase + lr) * EE + lc;
    const float* Bptr = B + (size_t)(colBase + lr) * EE + lc;

    for (int k0 = 0; k0 < EE; k0 += 16) {
        float4 a0 = *(const float4*)(Aptr + k0);
        float4 a1 = *(const float4*)(Aptr + (size_t)64 * EE + k0);
        float4 b0 = *(const float4*)(Bptr + k0);
        float4 b1 = *(const float4*)(Bptr + (size_t)64 * EE + k0);

        __syncthreads();   // protect previous-iteration smem reads
        As[lc + 0][lr]      = a0.x; As[lc + 1][lr]      = a0.y;
        As[lc + 2][lr]      = a0.z; As[lc + 3][lr]      = a0.w;
        As[lc + 0][lr + 64] = a1.x; As[lc + 1][lr + 64] = a1.y;
        As[lc + 2][lr + 64] = a1.z; As[lc + 3][lr + 64] = a1.w;
        Bs[lc + 0][lr]      = b0.x; Bs[lc + 1][lr]      = b0.y;
        Bs[lc + 2][lr]      = b0.z; Bs[lc + 3][lr]      = b0.w;
        Bs[lc + 0][lr + 64] = b1.x; Bs[lc + 1][lr + 64] = b1.y;
        Bs[lc + 2][lr + 64] = b1.z; Bs[lc + 3][lr + 64] = b1.w;
        __syncthreads();

#pragma unroll
        for (int kk = 0; kk < 16; kk++) {
            float4 ra0 = *(const float4*)&As[kk][ty * 8];
            float4 ra1 = *(const float4*)&As[kk][ty * 8 + 4];
            float4 rb0 = *(const float4*)&Bs[kk][tx * 8];
            float4 rb1 = *(const float4*)&Bs[kk][tx * 8 + 4];
            float ra[8] = {ra0.x, ra0.y, ra0.z, ra0.w, ra1.x, ra1.y, ra1.z, ra1.w};
            float rb[8] = {rb0.x, rb0.y, rb0.z, rb0.w, rb1.x, rb1.y, rb1.z, rb1.w};
#pragma unroll
            for (int i = 0; i < 8; i++)
#pragma unroll
                for (int j = 0; j < 8; j++)
                    acc[i][j] = fmaf(ra[i], rb[j], acc[i][j]);
        }
    }

    float bj[8];
#pragma unroll
    for (int j = 0; j < 8; j++)
        bj[j] = bias ? bias[colBase + tx * 8 + j] : 0.f;

#pragma unroll
    for (int i = 0; i < 8; i++) {
        const size_t row = (size_t)(rowBase + ty * 8 + i);
        float4 c0, c1;
        c0.x = acc[i][0] + bj[0]; c0.y = acc[i][1] + bj[1];
        c0.z = acc[i][2] + bj[2]; c0.w = acc[i][3] + bj[3];
        c1.x = acc[i][4] + bj[4]; c1.y = acc[i][5] + bj[5];
        c1.z = acc[i][6] + bj[6]; c1.w = acc[i][7] + bj[7];
        *(float4*)&C[row * EE + colBase + tx * 8]     = c0;
        *(float4*)&C[row * EE + colBase + tx * 8 + 4] = c1;
    }
}

// ---------------------------------------------------------------------------
// Flash-style block-diagonal attention.
// grid: (LL/64, HH, NSEG). block: 256 threads.
// Each block: 64 q-rows x D=64 for one (segment, head).
// Thread (ty,tx) owns rows {ty+16i} and cols/dims {tx+16j}, i,j in 0..3.
// Online softmax stats (m,l) live in registers, replicated across the
// 16-lane row group via shfl reductions. O accumulator in registers.
// ---------------------------------------------------------------------------
#define SROW 68   // padded smem row stride (floats), 16B-aligned, conflict-free

__global__ __launch_bounds__(256)
void attn_kernel(const float* __restrict__ mask)
{
    extern __shared__ float sm[];
    float* Qs = sm;                 // [64][SROW]
    float* Ks = Qs + 64 * SROW;
    float* Vs = Ks + 64 * SROW;
    float* Ss = Vs + 64 * SROW;

    const int seg = blockIdx.z;
    const int h   = blockIdx.y;
    const int q0  = blockIdx.x * 64;
    const int tid = threadIdx.x;
    const int ty  = tid >> 4;
    const int tx  = tid & 15;

    const float scaling = 0.125f;   // D^-0.5, D=64

    // Load + pre-scale Q tile
    for (int i = tid; i < 64 * 16; i += 256) {
        const int r = i >> 4, c4 = (i & 15) * 4;
        float4 qv = *(const float4*)&g_q[(size_t)(seg * LL + q0 + r) * EE + h * DD + c4];
        qv.x *= scaling; qv.y *= scaling; qv.z *= scaling; qv.w *= scaling;
        *(float4*)&Qs[r * SROW + c4] = qv;
    }

    float o[4][4];
    float mrow[4], lrow[4];
#pragma unroll
    for (int i = 0; i < 4; i++) {
        mrow[i] = -INFINITY; lrow[i] = 0.f;
#pragma unroll
        for (int j = 0; j < 4; j++) o[i][j] = 0.f;
    }

    for (int kt = 0; kt < 16; kt++) {
        const int k0g = kt * 64;
        __syncthreads();   // previous-iteration Ks/Vs/Ss reads done
        for (int i = tid; i < 64 * 16; i += 256) {
            const int r = i >> 4, c4 = (i & 15) * 4;
            const size_t src = (size_t)(seg * LL + k0g + r) * EE + h * DD + c4;
            *(float4*)&Ks[r * SROW + c4] = *(const float4*)&g_k[src];
            *(float4*)&Vs[r * SROW + c4] = *(const float4*)&g_v[src];
        }
        __syncthreads();

        // S = (Q*scaling) @ K^T  (4x4 per thread, strided rows/cols)
        float s[4][4];
#pragma unroll
        for (int i = 0; i < 4; i++)
#pragma unroll
            for (int j = 0; j < 4; j++) s[i][j] = 0.f;

#pragma unroll
        for (int d = 0; d < 64; d += 4) {
            float4 qv[4], kv[4];
#pragma unroll
            for (int i = 0; i < 4; i++) qv[i] = *(const float4*)&Qs[(ty + 16 * i) * SROW + d];
#pragma unroll
            for (int j = 0; j < 4; j++) kv[j] = *(const float4*)&Ks[(tx + 16 * j) * SROW + d];
#pragma unroll
            for (int i = 0; i < 4; i++)
#pragma unroll
                for (int j = 0; j < 4; j++) {
                    s[i][j] = fmaf(qv[i].x, kv[j].x, s[i][j]);
                    s[i][j] = fmaf(qv[i].y, kv[j].y, s[i][j]);
                    s[i][j] = fmaf(qv[i].z, kv[j].z, s[i][j]);
                    s[i][j] = fmaf(qv[i].w, kv[j].w, s[i][j]);
                }
        }

        // + block-diagonal mask slice
#pragma unroll
        for (int i = 0; i < 4; i++) {
            const size_t mr = (size_t)(seg * LL + q0 + ty + 16 * i) * TT + seg * LL + k0g;
#pragma unroll
            for (int j = 0; j < 4; j++)
                s[i][j] += mask[mr + tx + 16 * j];
        }

        // Online softmax update, per owned row
        float alpha[4];
#pragma unroll
        for (int i = 0; i < 4; i++) {
            float mt = fmaxf(fmaxf(s[i][0], s[i][1]), fmaxf(s[i][2], s[i][3]));
#pragma unroll
            for (int w = 1; w < 16; w <<= 1)
                mt = fmaxf(mt, __shfl_xor_sync(0xffffffffu, mt, w, 16));
            const float mnew = fmaxf(mrow[i], mt);
            alpha[i] = __expf(mrow[i] - mnew);
            mrow[i]  = mnew;
            float rs = 0.f;
#pragma unroll
            for (int j = 0; j < 4; j++) {
                const float p = __expf(s[i][j] - mnew);
                s[i][j] = p;
                rs += p;
            }
#pragma unroll
            for (int w = 1; w < 16; w <<= 1)
                rs += __shfl_xor_sync(0xffffffffu, rs, w, 16);
            lrow[i] = lrow[i] * alpha[i] + rs;
        }

        // Write P, rescale O
#pragma unroll
        for (int i = 0; i < 4; i++) {
#pragma unroll
            for (int j = 0; j < 4; j++)
                Ss[(ty + 16 * i) * SROW + tx + 16 * j] = s[i][j];
#pragma unroll
            for (int j = 0; j < 4; j++) o[i][j] *= alpha[i];
        }
        __syncthreads();

        // O += P @ V
#pragma unroll
        for (int c = 0; c < 64; c += 4) {
            float4 p4[4];
#pragma unroll
            for (int i = 0; i < 4; i++)
                p4[i] = *(const float4*)&Ss[(ty + 16 * i) * SROW + c];
#pragma unroll
            for (int cc = 0; cc < 4; cc++) {
                float vv[4];
#pragma unroll
                for (int j = 0; j < 4; j++)
                    vv[j] = Vs[(c + cc) * SROW + tx + 16 * j];
#pragma unroll
                for (int i = 0; i < 4; i++) {
                    const float pi = ((const float*)&p4[i])[cc];
#pragma unroll
                    for (int j = 0; j < 4; j++)
                        o[i][j] = fmaf(pi, vv[j], o[i][j]);
                }
            }
        }
    }

    // Normalize and write
#pragma unroll
    for (int i = 0; i < 4; i++) {
        const float inv = 1.f / lrow[i];
        const size_t row = (size_t)(seg * LL + q0 + ty + 16 * i);
#pragma unroll
        for (int j = 0; j < 4; j++)
            g_ao[row * EE + h * DD + tx + 16 * j] = o[i][j] * inv;
    }
}

// ---------------------------------------------------------------------------

extern "C" void kernel_launch(void* const* d_in, const int* in_sizes, int n_in,
                              void* d_out, int out_size)
{
    const float* hs   = (const float*)d_in[0];
    // d_in[1] = cu_seqlens (uniform segments, constants baked in)
    const float* mask = (const float*)d_in[2];
    const float* wq   = (const float*)d_in[3];
    const float* bq   = (const float*)d_in[4];
    const float* wk   = (const float*)d_in[5];
    const float* wv   = (const float*)d_in[6];
    const float* bv   = (const float*)d_in[7];
    const float* wo   = (const float*)d_in[8];
    const float* bo   = (const float*)d_in[9];
    float* out = (float*)d_out;

    float *qp, *kp, *vp, *aop;
    cudaGetSymbolAddress((void**)&qp,  g_q);
    cudaGetSymbolAddress((void**)&kp,  g_k);
    cudaGetSymbolAddress((void**)&vp,  g_v);
    cudaGetSymbolAddress((void**)&aop, g_ao);

    const dim3 gg(EE / 128, TT / 128);

    gemm_nt<<<gg, 256>>>(hs, wq, bq,      qp);
    gemm_nt<<<gg, 256>>>(hs, wk, nullptr, kp);
    gemm_nt<<<gg, 256>>>(hs, wv, bv,      vp);

    const int smem = 4 * 64 * SROW * (int)sizeof(float);
    cudaFuncSetAttribute(attn_kernel, cudaFuncAttributeMaxDynamicSharedMemorySize, smem);
    attn_kernel<<<dim3(LL / 64, HH, NSEG), 256, smem>>>(mask);

    gemm_nt<<<gg, 256>>>(aop, wo, bo, out);
}

// round 2
// speedup vs baseline: 1.1086x; 1.1086x over previous
#include <cuda_runtime.h>
#include <math.h>
#include <stdint.h>

#define TT   8192
#define EE   1024
#define HH   16
#define DD   64
#define NSEG 8
#define LL   1024

// Scratch (device globals — no allocation allowed in kernel_launch)
__device__ float g_q  [TT * EE];
__device__ float g_k  [TT * EE];
__device__ float g_v  [TT * EE];
__device__ float g_ao [TT * EE];
__device__ float g_at [TT * EE];   // tf32-rounded activations (hs, then ao)
__device__ float g_wt [EE * EE];   // tf32-rounded weight (reused per GEMM)

// ---------------------------------------------------------------------------
// Elementwise round-to-nearest tf32 (keeps fp32 bit layout, low mantissa zeroed)
// ---------------------------------------------------------------------------
__global__ void round_tf32_kernel(const float* __restrict__ in,
                                  float* __restrict__ out, int n4)
{
    int i = blockIdx.x * blockDim.x + threadIdx.x;
    if (i >= n4) return;
    float4 v = ((const float4*)in)[i];
    uint32_t r0, r1, r2, r3;
    asm("cvt.rna.tf32.f32 %0, %1;" : "=r"(r0) : "f"(v.x));
    asm("cvt.rna.tf32.f32 %0, %1;" : "=r"(r1) : "f"(v.y));
    asm("cvt.rna.tf32.f32 %0, %1;" : "=r"(r2) : "f"(v.z));
    asm("cvt.rna.tf32.f32 %0, %1;" : "=r"(r3) : "f"(v.w));
    float4 o;
    o.x = __uint_as_float(r0); o.y = __uint_as_float(r1);
    o.z = __uint_as_float(r2); o.w = __uint_as_float(r3);
    ((float4*)out)[i] = o;
}

// ---------------------------------------------------------------------------
// TF32 tensor-core GEMM: C[M,N] = A[M,K] @ B[N,K]^T + bias
// M=8192, N=K=1024. A,B pre-rounded to tf32.
// 128x128x32 block tile, 8 warps (2x4), warp tile 64x32, m16n8k8 mma.
// cp.async double-buffered smem, padded stride 36 floats (conflict-free LDSM).
// ---------------------------------------------------------------------------
#define GSA 36                     // smem row stride in floats
#define BUF_FLOATS (128 * GSA)     // one operand tile
#define BUF_BYTES  (2 * BUF_FLOATS * 4)  // A+B per stage

__device__ __forceinline__ void cp_async16(uint32_t dst, const void* src) {
    asm volatile("cp.async.cg.shared.global [%0], [%1], 16;\n" :: "r"(dst), "l"(src));
}
__device__ __forceinline__ void cp_commit() {
    asm volatile("cp.async.commit_group;\n");
}
template <int N>
__device__ __forceinline__ void cp_wait() {
    asm volatile("cp.async.wait_group %0;\n" :: "n"(N));
}

__global__ __launch_bounds__(256, 2)
void gemm_tc(const float* __restrict__ A, const float* __restrict__ B,
             const float* __restrict__ bias, float* __restrict__ C)
{
    extern __shared__ float sm[];
    const uint32_t smemBase = (uint32_t)__cvta_generic_to_shared(sm);

    const int tid  = threadIdx.x;
    const int warp = tid >> 5;
    const int lane = tid & 31;
    const int rowBase = blockIdx.y * 128;
    const int colBase = blockIdx.x * 128;

    const int mW = (warp >> 2) * 64;
    const int nW = (warp & 3) * 32;

    // loader indices: 32 rows x 8 chunks(16B) per pass, 4 passes
    const int lrow = tid >> 3;         // 0..31
    const int lch  = (tid & 7) * 4;    // float offset of 16B chunk

    // fragment smem byte offsets within a buffer
    int aoff[4], boff[4];
#pragma unroll
    for (int mi = 0; mi < 4; mi++)
        aoff[mi] = (((mW + mi * 16 + (lane & 15)) * GSA) + ((lane >> 4) << 2)) << 2;
#pragma unroll
    for (int nj = 0; nj < 4; nj++)
        boff[nj] = (((nW + nj * 8 + (lane & 7)) * GSA) + (((lane >> 3) & 1) << 2)) << 2;

    float c[4][4][4];
#pragma unroll
    for (int mi = 0; mi < 4; mi++)
#pragma unroll
        for (int nj = 0; nj < 4; nj++)
#pragma unroll
            for (int r = 0; r < 4; r++) c[mi][nj][r] = 0.f;

    const float* Abase = A + (size_t)(rowBase + lrow) * EE + lch;
    const float* Bbase = B + (size_t)(colBase + lrow) * EE + lch;
    const uint32_t sA0 = smemBase + ((lrow * GSA + lch) << 2);
    const uint32_t sB0 = sA0 + BUF_FLOATS * 4;

    const int NSLAB = EE / 32;

    // prologue: slab 0 -> buffer 0
    {
#pragma unroll
        for (int p = 0; p < 4; p++) {
            cp_async16(sA0 + p * 32 * GSA * 4, Abase + (size_t)p * 32 * EE);
            cp_async16(sB0 + p * 32 * GSA * 4, Bbase + (size_t)p * 32 * EE);
        }
        cp_commit();
    }

    for (int s = 0; s < NSLAB; s++) {
        // prefetch slab s+1 into buffer (s+1)&1
        if (s + 1 < NSLAB) {
            const int k0 = (s + 1) * 32;
            const uint32_t bufOff = ((s + 1) & 1) * BUF_BYTES;
#pragma unroll
            for (int p = 0; p < 4; p++) {
                cp_async16(sA0 + bufOff + p * 32 * GSA * 4, Abase + (size_t)p * 32 * EE + k0);
                cp_async16(sB0 + bufOff + p * 32 * GSA * 4, Bbase + (size_t)p * 32 * EE + k0);
            }
        }
        cp_commit();
        cp_wait<1>();          // slab s resident
        __syncthreads();

        const uint32_t aB = smemBase + (s & 1) * BUF_BYTES;
        const uint32_t bB = aB + BUF_FLOATS * 4;

#pragma unroll
        for (int kk = 0; kk < 4; kk++) {
            const uint32_t ko = kk * 32;   // 8 floats
            uint32_t a[4][4], b[4][2];
#pragma unroll
            for (int mi = 0; mi < 4; mi++)
                asm volatile("ldmatrix.sync.aligned.m8n8.x4.shared.b16 {%0,%1,%2,%3}, [%4];"
                             : "=r"(a[mi][0]), "=r"(a[mi][1]), "=r"(a[mi][2]), "=r"(a[mi][3])
                             : "r"(aB + aoff[mi] + ko));
#pragma unroll
            for (int nj = 0; nj < 4; nj++)
                asm volatile("ldmatrix.sync.aligned.m8n8.x2.shared.b16 {%0,%1}, [%2];"
                             : "=r"(b[nj][0]), "=r"(b[nj][1])
                             : "r"(bB + boff[nj] + ko));
#pragma unroll
            for (int mi = 0; mi < 4; mi++)
#pragma unroll
                for (int nj = 0; nj < 4; nj++)
                    asm volatile(
                        "mma.sync.aligned.m16n8k8.row.col.f32.tf32.tf32.f32 "
                        "{%0,%1,%2,%3}, {%4,%5,%6,%7}, {%8,%9}, {%0,%1,%2,%3};"
                        : "+f"(c[mi][nj][0]), "+f"(c[mi][nj][1]),
                          "+f"(c[mi][nj][2]), "+f"(c[mi][nj][3])
                        : "r"(a[mi][0]), "r"(a[mi][1]), "r"(a[mi][2]), "r"(a[mi][3]),
                          "r"(b[nj][0]), "r"(b[nj][1]));
        }
        __syncthreads();
    }

    // epilogue
#pragma unroll
    for (int nj = 0; nj < 4; nj++) {
        const int col = colBase + nW + nj * 8 + (lane & 3) * 2;
        float b0 = bias ? bias[col]     : 0.f;
        float b1 = bias ? bias[col + 1] : 0.f;
#pragma unroll
        for (int mi = 0; mi < 4; mi++) {
            const int row = rowBase + mW + mi * 16 + (lane >> 2);
            float2 v0 = {c[mi][nj][0] + b0, c[mi][nj][1] + b1};
            float2 v1 = {c[mi][nj][2] + b0, c[mi][nj][3] + b1};
            *(float2*)&C[(size_t)row * EE + col]       = v0;
            *(float2*)&C[(size_t)(row + 8) * EE + col] = v1;
        }
    }
}

// ---------------------------------------------------------------------------
// Flash-style block-diagonal attention (unchanged from round 1).
// ---------------------------------------------------------------------------
#define SROW 68

__global__ __launch_bounds__(256)
void attn_kernel(const float* __restrict__ mask)
{
    extern __shared__ float sm[];
    float* Qs = sm;
    float* Ks = Qs + 64 * SROW;
    float* Vs = Ks + 64 * SROW;
    float* Ss = Vs + 64 * SROW;

    const int seg = blockIdx.z;
    const int h   = blockIdx.y;
    const int q0  = blockIdx.x * 64;
    const int tid = threadIdx.x;
    const int ty  = tid >> 4;
    const int tx  = tid & 15;

    const float scaling = 0.125f;

    for (int i = tid; i < 64 * 16; i += 256) {
        const int r = i >> 4, c4 = (i & 15) * 4;
        float4 qv = *(const float4*)&g_q[(size_t)(seg * LL + q0 + r) * EE + h * DD + c4];
        qv.x *= scaling; qv.y *= scaling; qv.z *= scaling; qv.w *= scaling;
        *(float4*)&Qs[r * SROW + c4] = qv;
    }

    float o[4][4];
    float mrow[4], lrow[4];
#pragma unroll
    for (int i = 0; i < 4; i++) {
        mrow[i] = -INFINITY; lrow[i] = 0.f;
#pragma unroll
        for (int j = 0; j < 4; j++) o[i][j] = 0.f;
    }

    for (int kt = 0; kt < 16; kt++) {
        const int k0g = kt * 64;
        __syncthreads();
        for (int i = tid; i < 64 * 16; i += 256) {
            const int r = i >> 4, c4 = (i & 15) * 4;
            const size_t src = (size_t)(seg * LL + k0g + r) * EE + h * DD + c4;
            *(float4*)&Ks[r * SROW + c4] = *(const float4*)&g_k[src];
            *(float4*)&Vs[r * SROW + c4] = *(const float4*)&g_v[src];
        }
        __syncthreads();

        float s[4][4];
#pragma unroll
        for (int i = 0; i < 4; i++)
#pragma unroll
            for (int j = 0; j < 4; j++) s[i][j] = 0.f;

#pragma unroll
        for (int d = 0; d < 64; d += 4) {
            float4 qv[4], kv[4];
#pragma unroll
            for (int i = 0; i < 4; i++) qv[i] = *(const float4*)&Qs[(ty + 16 * i) * SROW + d];
#pragma unroll
            for (int j = 0; j < 4; j++) kv[j] = *(const float4*)&Ks[(tx + 16 * j) * SROW + d];
#pragma unroll
            for (int i = 0; i < 4; i++)
#pragma unroll
                for (int j = 0; j < 4; j++) {
                    s[i][j] = fmaf(qv[i].x, kv[j].x, s[i][j]);
                    s[i][j] = fmaf(qv[i].y, kv[j].y, s[i][j]);
                    s[i][j] = fmaf(qv[i].z, kv[j].z, s[i][j]);
                    s[i][j] = fmaf(qv[i].w, kv[j].w, s[i][j]);
                }
        }

#pragma unroll
        for (int i = 0; i < 4; i++) {
            const size_t mr = (size_t)(seg * LL + q0 + ty + 16 * i) * TT + seg * LL + k0g;
#pragma unroll
            for (int j = 0; j < 4; j++)
                s[i][j] += mask[mr + tx + 16 * j];
        }

        float alpha[4];
#pragma unroll
        for (int i = 0; i < 4; i++) {
            float mt = fmaxf(fmaxf(s[i][0], s[i][1]), fmaxf(s[i][2], s[i][3]));
#pragma unroll
            for (int w = 1; w < 16; w <<= 1)
                mt = fmaxf(mt, __shfl_xor_sync(0xffffffffu, mt, w, 16));
            const float mnew = fmaxf(mrow[i], mt);
            alpha[i] = __expf(mrow[i] - mnew);
            mrow[i]  = mnew;
            float rs = 0.f;
#pragma unroll
            for (int j = 0; j < 4; j++) {
                const float p = __expf(s[i][j] - mnew);
                s[i][j] = p;
                rs += p;
            }
#pragma unroll
            for (int w = 1; w < 16; w <<= 1)
                rs += __shfl_xor_sync(0xffffffffu, rs, w, 16);
            lrow[i] = lrow[i] * alpha[i] + rs;
        }

#pragma unroll
        for (int i = 0; i < 4; i++) {
#pragma unroll
            for (int j = 0; j < 4; j++)
                Ss[(ty + 16 * i) * SROW + tx + 16 * j] = s[i][j];
#pragma unroll
            for (int j = 0; j < 4; j++) o[i][j] *= alpha[i];
        }
        __syncthreads();

#pragma unroll
        for (int cb = 0; cb < 64; cb += 4) {
            float4 p4[4];
#pragma unroll
            for (int i = 0; i < 4; i++)
                p4[i] = *(const float4*)&Ss[(ty + 16 * i) * SROW + cb];
#pragma unroll
            for (int cc = 0; cc < 4; cc++) {
                float vv[4];
#pragma unroll
                for (int j = 0; j < 4; j++)
                    vv[j] = Vs[(cb + cc) * SROW + tx + 16 * j];
#pragma unroll
                for (int i = 0; i < 4; i++) {
                    const float pi = ((const float*)&p4[i])[cc];
#pragma unroll
                    for (int j = 0; j < 4; j++)
                        o[i][j] = fmaf(pi, vv[j], o[i][j]);
                }
            }
        }
    }

#pragma unroll
    for (int i = 0; i < 4; i++) {
        const float inv = 1.f / lrow[i];
        const size_t row = (size_t)(seg * LL + q0 + ty + 16 * i);
#pragma unroll
        for (int j = 0; j < 4; j++)
            g_ao[row * EE + h * DD + tx + 16 * j] = o[i][j] * inv;
    }
}

// ---------------------------------------------------------------------------

extern "C" void kernel_launch(void* const* d_in, const int* in_sizes, int n_in,
                              void* d_out, int out_size)
{
    const float* hs   = (const float*)d_in[0];
    const float* mask = (const float*)d_in[2];
    const float* wq   = (const float*)d_in[3];
    const float* bq   = (const float*)d_in[4];
    const float* wk   = (const float*)d_in[5];
    const float* wv   = (const float*)d_in[6];
    const float* bv   = (const float*)d_in[7];
    const float* wo   = (const float*)d_in[8];
    const float* bo   = (const float*)d_in[9];
    float* out = (float*)d_out;

    float *qp, *kp, *vp, *aop, *atp, *wtp;
    cudaGetSymbolAddress((void**)&qp,  g_q);
    cudaGetSymbolAddress((void**)&kp,  g_k);
    cudaGetSymbolAddress((void**)&vp,  g_v);
    cudaGetSymbolAddress((void**)&aop, g_ao);
    cudaGetSymbolAddress((void**)&atp, g_at);
    cudaGetSymbolAddress((void**)&wtp, g_wt);

    const int gemmSmem = (int)BUF_BYTES * 2;  // 73728
    cudaFuncSetAttribute(gemm_tc, cudaFuncAttributeMaxDynamicSharedMemorySize, gemmSmem);

    const dim3 gg(EE / 128, TT / 128);
    const int nAct4 = TT * EE / 4;
    const int nW4   = EE * EE / 4;

    // round activations once
    round_tf32_kernel<<<nAct4 / 256, 256>>>(hs, atp, nAct4);

    // Q
    round_tf32_kernel<<<nW4 / 256, 256>>>(wq, wtp, nW4);
    gemm_tc<<<gg, 256, gemmSmem>>>(atp, wtp, bq, qp);
    // K
    round_tf32_kernel<<<nW4 / 256, 256>>>(wk, wtp, nW4);
    gemm_tc<<<gg, 256, gemmSmem>>>(atp, wtp, nullptr, kp);
    // V
    round_tf32_kernel<<<nW4 / 256, 256>>>(wv, wtp, nW4);
    gemm_tc<<<gg, 256, gemmSmem>>>(atp, wtp, bv, vp);

    // attention
    const int asmem = 4 * 64 * SROW * (int)sizeof(float);
    cudaFuncSetAttribute(attn_kernel, cudaFuncAttributeMaxDynamicSharedMemorySize, asmem);
    attn_kernel<<<dim3(LL / 64, HH, NSEG), 256, asmem>>>(mask);

    // output projection
    round_tf32_kernel<<<nAct4 / 256, 256>>>(aop, atp, nAct4);
    round_tf32_kernel<<<nW4 / 256, 256>>>(wo, wtp, nW4);
    gemm_tc<<<gg, 256, gemmSmem>>>(atp, wtp, bo, out);
}